// round 1
// baseline (speedup 1.0000x reference)
#include <cuda_runtime.h>
#include <cuda_bf16.h>
#include <mma.h>

using namespace nvcuda;

// Problem constants (dataset-fixed)
#define NBATCH 65536
#define NNODE  10
#define KD     512     // D
#define HD     64      // H
#define NC     128     // 2*H  (pa | pb)
#define MROWS  (NBATCH * NNODE)   // 655360

// Scratch: P[b, n, c] = pa (c<64) | pb (c>=64), fp32.  335 MB static device array.
__device__ float g_P[(size_t)MROWS * NC];

// triu_indices(10, k=1)
__constant__ int c_I[45] = {0,0,0,0,0,0,0,0,0, 1,1,1,1,1,1,1,1, 2,2,2,2,2,2,2,
                            3,3,3,3,3,3, 4,4,4,4,4, 5,5,5,5, 6,6,6, 7,7, 8};
__constant__ int c_J[45] = {1,2,3,4,5,6,7,8,9, 2,3,4,5,6,7,8,9, 3,4,5,6,7,8,9,
                            4,5,6,7,8,9, 5,6,7,8,9, 6,7,8,9, 7,8,9, 8,9, 9};

// fp32 -> (hi, lo) bf16 split: x ~= hi + lo with ~2^-17 residual.
__device__ __forceinline__ void bf16_split(float x, __nv_bfloat16& h, __nv_bfloat16& l) {
    h = __float2bfloat16(x);
    l = __float2bfloat16(x - __bfloat162float(h));
}

// =====================================================================
// Kernel 1: P = X @ Wcat   (M=655360, K=512, N=128), bf16 3-split WMMA.
// Wcat[k][c] = W1[k + 512*(c>=64)][c & 63]   (W1 is [1024][64] row-major)
// Block tile 128x128, BK=32, 256 threads (8 warps: 4 along M x 2 along N).
// Warp tile 32x64 -> 2x4 wmma 16x16x16 fragments.
// =====================================================================
__global__ __launch_bounds__(256, 1)
void gemm_split_kernel(const float* __restrict__ X, const float* __restrict__ W1) {
    __shared__ __align__(16) __nv_bfloat16 Ahi[128][48];
    __shared__ __align__(16) __nv_bfloat16 Alo[128][48];
    __shared__ __align__(16) __nv_bfloat16 Bhi[32][144];
    __shared__ __align__(16) __nv_bfloat16 Blo[32][144];

    const int tid  = threadIdx.x;
    const int warp = tid >> 5;
    const int wm   = warp & 3;   // 0..3  (M direction)
    const int wn   = warp >> 2;  // 0..1  (N direction)
    const long long row0 = (long long)blockIdx.x * 128;

    wmma::fragment<wmma::accumulator, 16, 16, 16, float> acc[2][4];
    #pragma unroll
    for (int i = 0; i < 2; i++)
        #pragma unroll
        for (int j = 0; j < 4; j++)
            wmma::fill_fragment(acc[i][j], 0.0f);

    for (int kc = 0; kc < KD; kc += 32) {
        // ---- load + split A tile: 128 rows x 32 k, 1024 float4 slots ----
        #pragma unroll
        for (int it = 0; it < 4; it++) {
            int s = tid + it * 256;      // 0..1023
            int m = s >> 3;              // row in tile
            int f = s & 7;               // float4 within row
            const float4 v = *(const float4*)(X + (row0 + m) * (long long)KD + kc + f * 4);
            __nv_bfloat16 h0, l0, h1, l1, h2, l2, h3, l3;
            bf16_split(v.x, h0, l0);
            bf16_split(v.y, h1, l1);
            bf16_split(v.z, h2, l2);
            bf16_split(v.w, h3, l3);
            *(__nv_bfloat162*)&Ahi[m][f * 4 + 0] = __halves2bfloat162(h0, h1);
            *(__nv_bfloat162*)&Ahi[m][f * 4 + 2] = __halves2bfloat162(h2, h3);
            *(__nv_bfloat162*)&Alo[m][f * 4 + 0] = __halves2bfloat162(l0, l1);
            *(__nv_bfloat162*)&Alo[m][f * 4 + 2] = __halves2bfloat162(l2, l3);
        }
        // ---- load + split B tile: 32 k x 128 cols ----
        #pragma unroll
        for (int it = 0; it < 4; it++) {
            int s = tid + it * 256;      // 0..1023
            int k = s >> 5;              // k row in tile
            int f = s & 31;              // float4 within row
            int c = f * 4;               // column 0..124 (4-group never crosses the 64 boundary)
            const float* src = W1 + ((long long)(kc + k) + (c >= 64 ? 512 : 0)) * 64 + (c & 63);
            const float4 v = *(const float4*)src;
            __nv_bfloat16 h0, l0, h1, l1, h2, l2, h3, l3;
            bf16_split(v.x, h0, l0);
            bf16_split(v.y, h1, l1);
            bf16_split(v.z, h2, l2);
            bf16_split(v.w, h3, l3);
            *(__nv_bfloat162*)&Bhi[k][c + 0] = __halves2bfloat162(h0, h1);
            *(__nv_bfloat162*)&Bhi[k][c + 2] = __halves2bfloat162(h2, h3);
            *(__nv_bfloat162*)&Blo[k][c + 0] = __halves2bfloat162(l0, l1);
            *(__nv_bfloat162*)&Blo[k][c + 2] = __halves2bfloat162(l2, l3);
        }
        __syncthreads();

        #pragma unroll
        for (int ks = 0; ks < 2; ks++) {
            wmma::fragment<wmma::matrix_b, 16, 16, 16, __nv_bfloat16, wmma::row_major> bh[4], bl[4];
            #pragma unroll
            for (int j = 0; j < 4; j++) {
                wmma::load_matrix_sync(bh[j], &Bhi[ks * 16][wn * 64 + j * 16], 144);
                wmma::load_matrix_sync(bl[j], &Blo[ks * 16][wn * 64 + j * 16], 144);
            }
            #pragma unroll
            for (int i = 0; i < 2; i++) {
                wmma::fragment<wmma::matrix_a, 16, 16, 16, __nv_bfloat16, wmma::row_major> ah, al;
                wmma::load_matrix_sync(ah, &Ahi[wm * 32 + i * 16][ks * 16], 48);
                wmma::load_matrix_sync(al, &Alo[wm * 32 + i * 16][ks * 16], 48);
                #pragma unroll
                for (int j = 0; j < 4; j++) {
                    wmma::mma_sync(acc[i][j], ah, bh[j], acc[i][j]);  // hi*hi
                    wmma::mma_sync(acc[i][j], ah, bl[j], acc[i][j]);  // hi*lo
                    wmma::mma_sync(acc[i][j], al, bh[j], acc[i][j]);  // lo*hi
                }
            }
        }
        __syncthreads();
    }

    #pragma unroll
    for (int i = 0; i < 2; i++)
        #pragma unroll
        for (int j = 0; j < 4; j++) {
            float* dst = g_P + (row0 + wm * 32 + i * 16) * (long long)NC + wn * 64 + j * 16;
            wmma::store_matrix_sync(dst, acc[i][j], NC, wmma::mem_row_major);
        }
}

// =====================================================================
// Kernel 2: per batch b: v_p = b2 + sum_h relu(pa[i_p,h] + pb[j_p,h] + b1[h]) * W2[h]
// then scatter symmetric 10x10 output (diag = 0).
// 256 threads = 4 batches x 64 threads. P rows cached in smem, row stride 129
// (129 % 32 == 1 -> distinct i map to distinct banks, same i broadcasts).
// =====================================================================
__global__ __launch_bounds__(256)
void pair_kernel(const float* __restrict__ b1, const float* __restrict__ W2,
                 const float* __restrict__ b2, float* __restrict__ out) {
    __shared__ float sp[4][NNODE * 129];
    __shared__ float sb1[HD], sw2[HD];
    __shared__ float vbuf[4][45];

    const int tid = threadIdx.x;
    const int g   = tid >> 6;    // batch slot in block
    const int lt  = tid & 63;
    const long long b = (long long)blockIdx.x * 4 + g;

    if (tid < HD) { sb1[tid] = b1[tid]; sw2[tid] = W2[tid]; }

    const float* Pb = g_P + b * (long long)(NNODE * NC);
    #pragma unroll
    for (int it = 0; it < 20; it++) {
        int idx = lt + it * 64;          // 0..1279
        int n = idx >> 7;
        int h = idx & 127;
        sp[g][n * 129 + h] = Pb[idx];
    }
    __syncthreads();

    const float bias2 = b2[0];
    if (lt < 45) {
        const int i = c_I[lt];
        const int j = c_J[lt];
        const float* pi = &sp[g][i * 129];        // pa row
        const float* pj = &sp[g][j * 129 + 64];   // pb row
        float acc = 0.0f;
        #pragma unroll
        for (int h = 0; h < HD; h++) {
            float x = pi[h] + pj[h] + sb1[h];
            acc = fmaf(fmaxf(x, 0.0f), sw2[h], acc);
        }
        vbuf[g][lt] = acc + bias2;
    }
    __syncthreads();

    // 100 outputs per batch, 64 threads -> 2 passes
    for (int o = lt; o < 100; o += 64) {
        int n1 = o / 10;
        int n2 = o % 10;
        float val = 0.0f;
        if (n1 != n2) {
            int i = n1 < n2 ? n1 : n2;
            int j = n1 < n2 ? n2 : n1;
            int p = 9 * i - (i * (i - 1)) / 2 + (j - i - 1);
            val = vbuf[g][p];
        }
        out[b * 100 + o] = val;
    }
}

extern "C" void kernel_launch(void* const* d_in, const int* in_sizes, int n_in,
                              void* d_out, int out_size) {
    const float* X  = (const float*)d_in[0];  // [B, 10, 512]
    const float* W1 = (const float*)d_in[1];  // [1024, 64]
    const float* b1 = (const float*)d_in[2];  // [64]
    const float* W2 = (const float*)d_in[3];  // [64, 1]
    const float* b2 = (const float*)d_in[4];  // [1]
    float* out = (float*)d_out;               // [B, 10, 10]

    const int Btot = in_sizes[0] / (NNODE * KD);   // 65536
    const int Mtot = Btot * NNODE;                 // 655360, divisible by 128

    gemm_split_kernel<<<Mtot / 128, 256>>>(X, W1);
    pair_kernel<<<Btot / 4, 256>>>(b1, W2, b2, out);
}

// round 3
// speedup vs baseline: 1.5063x; 1.5063x over previous
#include <cuda_runtime.h>
#include <cuda_bf16.h>
#include <mma.h>

using namespace nvcuda;

// ---------------- problem constants ----------------
#define NBATCH 65536
#define NNODE  10
#define KD     512
#define HD     64
#define NC     128                 // 2*H
#define MROWS  (NBATCH * NNODE)    // 655360
#define BPC    12                  // batches per CTA
#define RPC    120                 // valid rows per CTA
#define NCTA   ((NBATCH + BPC - 1) / BPC)   // 5462
#define NCHUNK 16                  // K chunks of 32

// Pre-split W, layout [k][n] (n = 0..127 contiguous), bf16 hi/lo.
__device__ __align__(128) __nv_bfloat16 g_Bh[KD * NC];
__device__ __align__(128) __nv_bfloat16 g_Bl[KD * NC];

__constant__ int c_I[45] = {0,0,0,0,0,0,0,0,0, 1,1,1,1,1,1,1,1, 2,2,2,2,2,2,2,
                            3,3,3,3,3,3, 4,4,4,4,4, 5,5,5,5, 6,6,6, 7,7, 8};
__constant__ int c_J[45] = {1,2,3,4,5,6,7,8,9, 2,3,4,5,6,7,8,9, 3,4,5,6,7,8,9,
                            4,5,6,7,8,9, 5,6,7,8,9, 6,7,8,9, 7,8,9, 8,9, 9};

// ---------------- helpers ----------------
__device__ __forceinline__ unsigned smem_u32(const void* p) {
    unsigned a;
    asm("{ .reg .u64 t; cvta.to.shared.u64 t, %1; cvt.u32.u64 %0, t; }" : "=r"(a) : "l"(p));
    return a;
}
__device__ __forceinline__ void cp16(unsigned dst, const void* src) {
    asm volatile("cp.async.cg.shared.global [%0], [%1], 16;" :: "r"(dst), "l"(src) : "memory");
}
#define CP_COMMIT() asm volatile("cp.async.commit_group;" ::: "memory")
#define CP_WAIT0()  asm volatile("cp.async.wait_group 0;" ::: "memory")

// ---------------- smem layout (dynamic) ----------------
// 0    : sb1[64] f32
// 256  : sw2[64] f32
// 512  : b2
// 1024 : 2 stages x 37888B  { Ahi[128][40] | Alo[128][40] | Bhi[32][136] | Blo[32][136] }  (bf16)
#define OFF_SB1   0
#define OFF_SW2   256
#define OFF_SB2   512
#define OFF_STAGE 1024
#define ST_AH 0
#define ST_AL 10240
#define ST_BH 20480
#define ST_BL 29184
#define STAGE_SZ  37888
#define A_STRIDE  40     // bf16 elements (80B row) -> conflict-free LDSM
#define B_STRIDE  136    // bf16 elements (272B row)
#define SMEM_BYTES (OFF_STAGE + 2 * STAGE_SZ)   // 76800
// epilogue overlay (over stage area): sp[128][132] f32, then vbuf[540]
#define SP_STRIDE 132
#define OFF_VBUF  (OFF_STAGE + 128 * SP_STRIDE * 4)

// ---------------- kernel 0: split W1 -> bf16 hi/lo, layout [k][n] ----------------
__global__ void splitB_kernel(const float* __restrict__ W1) {
    int idx = blockIdx.x * 256 + threadIdx.x;      // idx = k*128 + n
    if (idx >= KD * NC) return;
    int k = idx >> 7, n = idx & 127;
    float w = W1[((long long)k + (n >= HD ? KD : 0)) * HD + (n & (HD - 1))];
    // hi = RZ-truncate, lo = RN(residual): |w - hi - lo| <= 2^-17 |w|
    unsigned uh = __float_as_uint(w) & 0xffff0000u;
    float res = w - __uint_as_float(uh);
    g_Bh[idx] = __ushort_as_bfloat16((unsigned short)(uh >> 16));
    g_Bl[idx] = __float2bfloat16(res);
}

// split 4 fp32 -> packed hi (2 uints) and lo (2 uints)
__device__ __forceinline__ void split4(float4 a, unsigned& h0, unsigned& h1,
                                       unsigned& l0, unsigned& l1) {
    h0 = __byte_perm(__float_as_uint(a.x), __float_as_uint(a.y), 0x7632);
    h1 = __byte_perm(__float_as_uint(a.z), __float_as_uint(a.w), 0x7632);
    float r0 = a.x - __uint_as_float(__float_as_uint(a.x) & 0xffff0000u);
    float r1 = a.y - __uint_as_float(__float_as_uint(a.y) & 0xffff0000u);
    float r2 = a.z - __uint_as_float(__float_as_uint(a.z) & 0xffff0000u);
    float r3 = a.w - __uint_as_float(__float_as_uint(a.w) & 0xffff0000u);
    __nv_bfloat162 p0 = __floats2bfloat162_rn(r0, r1);
    __nv_bfloat162 p1 = __floats2bfloat162_rn(r2, r3);
    l0 = *(unsigned*)&p0;
    l1 = *(unsigned*)&p1;
}

// ---------------- fused GEMM (pipelined wmma) + pair epilogue ----------------
__global__ __launch_bounds__(256, 2)
void gemm_pair_kernel(const float* __restrict__ X,
                      const float* __restrict__ b1, const float* __restrict__ W2,
                      const float* __restrict__ b2, float* __restrict__ out) {
    extern __shared__ char smem[];
    const unsigned sb = smem_u32(smem);
    const int tid  = threadIdx.x;
    const int warp = tid >> 5;
    const int wm   = warp & 3;     // M direction (4)
    const int wn   = warp >> 2;    // N direction (2)
    const long long cta  = blockIdx.x;
    const long long row0 = cta * RPC;

    if (tid < HD) {
        ((float*)(smem + OFF_SB1))[tid] = b1[tid];
        ((float*)(smem + OFF_SW2))[tid] = W2[tid];
    }
    if (tid == 0) ((float*)(smem + OFF_SB2))[0] = b2[0];

    // ---- per-thread load coordinates ----
    // A: row r = tid/2, half = tid&1 -> 16 floats (4 float4) per chunk
    const int r    = tid >> 1;
    const int half = tid & 1;
    long long grow = row0 + r;
    if (grow >= MROWS) grow = MROWS - 1;      // tail CTA clamp (rows unused)
    const float* xrow = X + grow * KD + half * 16;
    const unsigned aoff = (unsigned)(r * (A_STRIDE * 2) + half * 32);  // byte offset
    // B: k row = tid/8, two 16B groups g and g+8
    const int bk = tid >> 3;
    const int bg = tid & 7;
    const unsigned boff0 = (unsigned)(bk * (B_STRIDE * 2) + bg * 16);
    const unsigned boff1 = boff0 + 128;       // (bg+8)*16

    wmma::fragment<wmma::accumulator, 16, 16, 16, float> acc[2][4];
    #pragma unroll
    for (int i = 0; i < 2; i++)
        #pragma unroll
        for (int j = 0; j < 4; j++)
            wmma::fill_fragment(acc[i][j], 0.0f);

    // ---- prologue: stage chunk 0 into buffer 0 ----
    {
        const unsigned stg = sb + OFF_STAGE;
        const __nv_bfloat16* bh = g_Bh + bk * NC;
        const __nv_bfloat16* bl = g_Bl + bk * NC;
        cp16(stg + ST_BH + boff0, bh + bg * 8);
        cp16(stg + ST_BH + boff1, bh + (bg + 8) * 8);
        cp16(stg + ST_BL + boff0, bl + bg * 8);
        cp16(stg + ST_BL + boff1, bl + (bg + 8) * 8);
        CP_COMMIT();
        const float4* p = (const float4*)xrow;
        #pragma unroll
        for (int q = 0; q < 2; q++) {
            unsigned h0, h1, h2, h3, l0, l1, l2, l3;
            split4(p[2 * q],     h0, h1, l0, l1);
            split4(p[2 * q + 1], h2, h3, l2, l3);
            uint4 hv = make_uint4(h0, h1, h2, h3);
            uint4 lv = make_uint4(l0, l1, l2, l3);
            asm volatile("st.shared.v4.b32 [%0], {%1,%2,%3,%4};"
                         :: "r"(stg + ST_AH + aoff + q * 16), "r"(hv.x), "r"(hv.y), "r"(hv.z), "r"(hv.w) : "memory");
            asm volatile("st.shared.v4.b32 [%0], {%1,%2,%3,%4};"
                         :: "r"(stg + ST_AL + aoff + q * 16), "r"(lv.x), "r"(lv.y), "r"(lv.z), "r"(lv.w) : "memory");
        }
        CP_WAIT0();
        __syncthreads();
    }

    // ---- main loop: mma chunk it from buf[it&1], stage it+1 into buf[~] ----
    #pragma unroll 1
    for (int it = 0; it < NCHUNK; ++it) {
        const unsigned stg  = sb + OFF_STAGE + (it & 1) * STAGE_SZ;
        const unsigned nstg = sb + OFF_STAGE + ((it + 1) & 1) * STAGE_SZ;

        float4 xa[4];
        if (it + 1 < NCHUNK) {
            const float4* p = (const float4*)(xrow + (it + 1) * 32);
            #pragma unroll
            for (int q = 0; q < 4; q++) xa[q] = p[q];
            const __nv_bfloat16* bh = g_Bh + ((it + 1) * 32 + bk) * NC;
            const __nv_bfloat16* bl = g_Bl + ((it + 1) * 32 + bk) * NC;
            cp16(nstg + ST_BH + boff0, bh + bg * 8);
            cp16(nstg + ST_BH + boff1, bh + (bg + 8) * 8);
            cp16(nstg + ST_BL + boff0, bl + bg * 8);
            cp16(nstg + ST_BL + boff1, bl + (bg + 8) * 8);
            CP_COMMIT();
        }

        // ---- mma over current stage ----
        const __nv_bfloat16* sAh = (const __nv_bfloat16*)(smem + (stg - sb) + ST_AH);
        const __nv_bfloat16* sAl = (const __nv_bfloat16*)(smem + (stg - sb) + ST_AL);
        const __nv_bfloat16* sBh = (const __nv_bfloat16*)(smem + (stg - sb) + ST_BH);
        const __nv_bfloat16* sBl = (const __nv_bfloat16*)(smem + (stg - sb) + ST_BL);
        #pragma unroll
        for (int ks = 0; ks < 2; ks++) {
            wmma::fragment<wmma::matrix_b, 16, 16, 16, __nv_bfloat16, wmma::row_major> bh[4], bl[4];
            #pragma unroll
            for (int j = 0; j < 4; j++) {
                wmma::load_matrix_sync(bh[j], sBh + ks * 16 * B_STRIDE + wn * 64 + j * 16, B_STRIDE);
                wmma::load_matrix_sync(bl[j], sBl + ks * 16 * B_STRIDE + wn * 64 + j * 16, B_STRIDE);
            }
            #pragma unroll
            for (int i = 0; i < 2; i++) {
                wmma::fragment<wmma::matrix_a, 16, 16, 16, __nv_bfloat16, wmma::row_major> ah, al;
                wmma::load_matrix_sync(ah, sAh + (wm * 32 + i * 16) * A_STRIDE + ks * 16, A_STRIDE);
                wmma::load_matrix_sync(al, sAl + (wm * 32 + i * 16) * A_STRIDE + ks * 16, A_STRIDE);
                #pragma unroll
                for (int j = 0; j < 4; j++) {
                    wmma::mma_sync(acc[i][j], ah, bh[j], acc[i][j]);
                    wmma::mma_sync(acc[i][j], ah, bl[j], acc[i][j]);
                    wmma::mma_sync(acc[i][j], al, bh[j], acc[i][j]);
                }
            }
        }

        if (it + 1 < NCHUNK) {
            // split + STS A(it+1)
            #pragma unroll
            for (int q = 0; q < 2; q++) {
                unsigned h0, h1, h2, h3, l0, l1, l2, l3;
                split4(xa[2 * q],     h0, h1, l0, l1);
                split4(xa[2 * q + 1], h2, h3, l2, l3);
                asm volatile("st.shared.v4.b32 [%0], {%1,%2,%3,%4};"
                             :: "r"(nstg + ST_AH + aoff + q * 16), "r"(h0), "r"(h1), "r"(h2), "r"(h3) : "memory");
                asm volatile("st.shared.v4.b32 [%0], {%1,%2,%3,%4};"
                             :: "r"(nstg + ST_AL + aoff + q * 16), "r"(l0), "r"(l1), "r"(l2), "r"(l3) : "memory");
            }
            CP_WAIT0();
        }
        __syncthreads();
    }

    // ---- epilogue: accumulators -> smem sp[128][132] ----
    float* sp = (float*)(smem + OFF_STAGE);
    #pragma unroll
    for (int i = 0; i < 2; i++)
        #pragma unroll
        for (int j = 0; j < 4; j++)
            wmma::store_matrix_sync(sp + (wm * 32 + i * 16) * SP_STRIDE + wn * 64 + j * 16,
                                    acc[i][j], SP_STRIDE, wmma::mem_row_major);
    __syncthreads();

    // ---- pair compute + symmetric scatter ----
    const int nb = (int)min((long long)BPC, (long long)NBATCH - cta * BPC);
    float* vbuf = (float*)(smem + OFF_VBUF);
    const float* sb1 = (const float*)(smem + OFF_SB1);
    const float* sw2 = (const float*)(smem + OFF_SW2);
    const float bias2 = ((const float*)(smem + OFF_SB2))[0];

    for (int p = tid; p < nb * 45; p += 256) {
        int bb = p / 45, q = p - bb * 45;
        const float* pi = sp + (bb * NNODE + c_I[q]) * SP_STRIDE;        // pa row
        const float* pj = sp + (bb * NNODE + c_J[q]) * SP_STRIDE + HD;   // pb row
        float acc2 = 0.0f;
        #pragma unroll
        for (int h = 0; h < HD; h++)
            acc2 = fmaf(fmaxf(pi[h] + pj[h] + sb1[h], 0.0f), sw2[h], acc2);
        vbuf[p] = acc2 + bias2;
    }
    __syncthreads();

    for (int o = tid; o < nb * 100; o += 256) {
        int bb = o / 100, cell = o - bb * 100;
        int n1 = cell / 10, n2 = cell % 10;
        float val = 0.0f;
        if (n1 != n2) {
            int i = n1 < n2 ? n1 : n2;
            int j = n1 < n2 ? n2 : n1;
            val = vbuf[bb * 45 + 9 * i - (i * (i - 1)) / 2 + (j - i - 1)];
        }
        out[(cta * BPC + bb) * 100 + cell] = val;
    }
}

extern "C" void kernel_launch(void* const* d_in, const int* in_sizes, int n_in,
                              void* d_out, int out_size) {
    const float* X  = (const float*)d_in[0];
    const float* W1 = (const float*)d_in[1];
    const float* b1 = (const float*)d_in[2];
    const float* W2 = (const float*)d_in[3];
    const float* b2 = (const float*)d_in[4];
    float* out = (float*)d_out;

    cudaFuncSetAttribute(gemm_pair_kernel,
                         cudaFuncAttributeMaxDynamicSharedMemorySize, SMEM_BYTES);

    splitB_kernel<<<(KD * NC + 255) / 256, 256>>>(W1);
    gemm_pair_kernel<<<NCTA, 256, SMEM_BYTES>>>(X, b1, W2, b2, out);
}

// round 4
// speedup vs baseline: 3.1140x; 2.0674x over previous
#include <cuda_runtime.h>
#include <cuda_fp16.h>
#include <mma.h>

using namespace nvcuda;

// ---------------- problem constants ----------------
#define NBATCH 65536
#define NNODE  10
#define KD     512
#define HD     64
#define NC     128                 // 2*H
#define MROWS  (NBATCH * NNODE)    // 655360
#define BPC    12                  // batches per CTA
#define RPC    120                 // valid rows per CTA
#define NCTA   ((NBATCH + BPC - 1) / BPC)   // 5462
#define NCHUNK 16                  // K chunks of 32

// W converted to fp16, layout [k][n] (n contiguous 0..127)
__device__ __align__(128) __half g_Bh[KD * NC];

__constant__ int c_I[45] = {0,0,0,0,0,0,0,0,0, 1,1,1,1,1,1,1,1, 2,2,2,2,2,2,2,
                            3,3,3,3,3,3, 4,4,4,4,4, 5,5,5,5, 6,6,6, 7,7, 8};
__constant__ int c_J[45] = {1,2,3,4,5,6,7,8,9, 2,3,4,5,6,7,8,9, 3,4,5,6,7,8,9,
                            4,5,6,7,8,9, 5,6,7,8,9, 6,7,8,9, 7,8,9, 8,9, 9};

// ---------------- helpers ----------------
__device__ __forceinline__ unsigned smem_u32(const void* p) {
    unsigned a;
    asm("{ .reg .u64 t; cvta.to.shared.u64 t, %1; cvt.u32.u64 %0, t; }" : "=r"(a) : "l"(p));
    return a;
}
__device__ __forceinline__ void cp16(unsigned dst, const void* src) {
    asm volatile("cp.async.cg.shared.global [%0], [%1], 16;" :: "r"(dst), "l"(src) : "memory");
}
#define CP_COMMIT() asm volatile("cp.async.commit_group;" ::: "memory")
#define CP_WAIT0()  asm volatile("cp.async.wait_group 0;" ::: "memory")

// ---------------- smem layout (dynamic) ----------------
// 0    : sb1[64] f32 ; 256: sw2[64] f32 ; 512: b2
// 1024 : 2 stages x 18944B { Ah[128][40] fp16 | Bh[32][136] fp16 }
#define OFF_SB1   0
#define OFF_SW2   256
#define OFF_SB2   512
#define OFF_STAGE 1024
#define ST_AH 0
#define ST_BH 10240
#define STAGE_SZ  18944
#define A_STRIDE  40     // half elements (80B row)
#define B_STRIDE  136    // half elements (272B row)
// epilogue overlay: sp[128][132] f32 at OFF_STAGE, vbuf[540] after it
#define SP_STRIDE 132
#define OFF_VBUF  (OFF_STAGE + 128 * SP_STRIDE * 4)
#define SMEM_BYTES (OFF_VBUF + 540 * 4)   // 70768 > GEMM need (38912)

// ---------------- kernel 0: W1 -> fp16, layout [k][n] ----------------
__global__ void convB_kernel(const float* __restrict__ W1) {
    int idx = blockIdx.x * 256 + threadIdx.x;      // idx = k*128 + n
    if (idx >= KD * NC) return;
    int k = idx >> 7, n = idx & 127;
    float w = W1[((long long)k + (n >= HD ? KD : 0)) * HD + (n & (HD - 1))];
    g_Bh[idx] = __float2half_rn(w);
}

// ---------------- fused GEMM (pipelined fp16 wmma) + pair epilogue ----------------
__global__ __launch_bounds__(256, 2)
void gemm_pair_kernel(const float* __restrict__ X,
                      const float* __restrict__ b1, const float* __restrict__ W2,
                      const float* __restrict__ b2, float* __restrict__ out) {
    extern __shared__ char smem[];
    const unsigned sb = smem_u32(smem);
    const int tid  = threadIdx.x;
    const int warp = tid >> 5;
    const int wm   = warp & 3;     // M direction (4)
    const int wn   = warp >> 2;    // N direction (2)
    const long long cta  = blockIdx.x;
    const long long row0 = cta * RPC;

    if (tid < HD) {
        ((float*)(smem + OFF_SB1))[tid] = b1[tid];
        ((float*)(smem + OFF_SW2))[tid] = W2[tid];
    }
    if (tid == 0) ((float*)(smem + OFF_SB2))[0] = b2[0];

    // ---- per-thread load coordinates ----
    // A: row r = tid/2, half-row h = tid&1 -> 16 floats (4 float4) per chunk
    const int r    = tid >> 1;
    const int half = tid & 1;
    long long grow = row0 + r;
    if (grow >= MROWS) grow = MROWS - 1;      // tail CTA clamp (extra rows unused)
    const float* xrow = X + grow * KD + half * 16;
    const unsigned aoff = (unsigned)(r * (A_STRIDE * 2) + half * 32);  // byte offset
    // B: k row = tid/8, 16B groups bg and bg+8
    const int bk = tid >> 3;
    const int bg = tid & 7;
    const unsigned boff0 = (unsigned)(bk * (B_STRIDE * 2) + bg * 16);
    const unsigned boff1 = boff0 + 128;

    wmma::fragment<wmma::accumulator, 16, 16, 16, float> acc[2][4];
    #pragma unroll
    for (int i = 0; i < 2; i++)
        #pragma unroll
        for (int j = 0; j < 4; j++)
            wmma::fill_fragment(acc[i][j], 0.0f);

    // convert 4 floats -> 2 packed half2 words
    auto cvt4 = [](float4 a, unsigned& u0, unsigned& u1) {
        __half2 p0 = __float22half2_rn(make_float2(a.x, a.y));
        __half2 p1 = __float22half2_rn(make_float2(a.z, a.w));
        u0 = *(unsigned*)&p0;
        u1 = *(unsigned*)&p1;
    };

    // ---- prologue: stage chunk 0 into buffer 0 ----
    {
        const unsigned stg = sb + OFF_STAGE;
        const __half* bh = g_Bh + bk * NC;
        cp16(stg + ST_BH + boff0, bh + bg * 8);
        cp16(stg + ST_BH + boff1, bh + (bg + 8) * 8);
        CP_COMMIT();
        const float4* p = (const float4*)xrow;
        #pragma unroll
        for (int q = 0; q < 2; q++) {
            unsigned u0, u1, u2, u3;
            cvt4(p[2 * q],     u0, u1);
            cvt4(p[2 * q + 1], u2, u3);
            asm volatile("st.shared.v4.b32 [%0], {%1,%2,%3,%4};"
                         :: "r"(stg + ST_AH + aoff + q * 16), "r"(u0), "r"(u1), "r"(u2), "r"(u3) : "memory");
        }
        CP_WAIT0();
        __syncthreads();
    }

    // ---- main loop ----
    #pragma unroll 1
    for (int it = 0; it < NCHUNK; ++it) {
        const unsigned stg  = sb + OFF_STAGE + (it & 1) * STAGE_SZ;
        const unsigned nstg = sb + OFF_STAGE + ((it + 1) & 1) * STAGE_SZ;

        float4 xa[4];
        if (it + 1 < NCHUNK) {
            const float4* p = (const float4*)(xrow + (it + 1) * 32);
            #pragma unroll
            for (int q = 0; q < 4; q++) xa[q] = p[q];
            const __half* bh = g_Bh + ((it + 1) * 32 + bk) * NC;
            cp16(nstg + ST_BH + boff0, bh + bg * 8);
            cp16(nstg + ST_BH + boff1, bh + (bg + 8) * 8);
            CP_COMMIT();
        }

        // ---- mma over current stage ----
        const __half* sAh = (const __half*)(smem + (stg - sb) + ST_AH);
        const __half* sBh = (const __half*)(smem + (stg - sb) + ST_BH);
        #pragma unroll
        for (int ks = 0; ks < 2; ks++) {
            wmma::fragment<wmma::matrix_b, 16, 16, 16, __half, wmma::row_major> bfr[4];
            #pragma unroll
            for (int j = 0; j < 4; j++)
                wmma::load_matrix_sync(bfr[j], sBh + ks * 16 * B_STRIDE + wn * 64 + j * 16, B_STRIDE);
            #pragma unroll
            for (int i = 0; i < 2; i++) {
                wmma::fragment<wmma::matrix_a, 16, 16, 16, __half, wmma::row_major> afr;
                wmma::load_matrix_sync(afr, sAh + (wm * 32 + i * 16) * A_STRIDE + ks * 16, A_STRIDE);
                #pragma unroll
                for (int j = 0; j < 4; j++)
                    wmma::mma_sync(acc[i][j], afr, bfr[j], acc[i][j]);
            }
        }

        if (it + 1 < NCHUNK) {
            #pragma unroll
            for (int q = 0; q < 2; q++) {
                unsigned u0, u1, u2, u3;
                cvt4(xa[2 * q],     u0, u1);
                cvt4(xa[2 * q + 1], u2, u3);
                asm volatile("st.shared.v4.b32 [%0], {%1,%2,%3,%4};"
                             :: "r"(nstg + ST_AH + aoff + q * 16), "r"(u0), "r"(u1), "r"(u2), "r"(u3) : "memory");
            }
            CP_WAIT0();
        }
        __syncthreads();
    }

    // ---- epilogue: accumulators -> smem sp[128][132] ----
    float* sp = (float*)(smem + OFF_STAGE);
    #pragma unroll
    for (int i = 0; i < 2; i++)
        #pragma unroll
        for (int j = 0; j < 4; j++)
            wmma::store_matrix_sync(sp + (wm * 32 + i * 16) * SP_STRIDE + wn * 64 + j * 16,
                                    acc[i][j], SP_STRIDE, wmma::mem_row_major);
    __syncthreads();

    // ---- pair compute + symmetric scatter ----
    const int nb = (int)min((long long)BPC, (long long)NBATCH - cta * BPC);
    float* vbuf = (float*)(smem + OFF_VBUF);
    const float* sb1 = (const float*)(smem + OFF_SB1);
    const float* sw2 = (const float*)(smem + OFF_SW2);
    const float bias2 = ((const float*)(smem + OFF_SB2))[0];

    for (int p = tid; p < nb * 45; p += 256) {
        int bb = p / 45, q = p - bb * 45;
        const float* pi = sp + (bb * NNODE + c_I[q]) * SP_STRIDE;        // pa row
        const float* pj = sp + (bb * NNODE + c_J[q]) * SP_STRIDE + HD;   // pb row
        float acc2 = 0.0f;
        #pragma unroll
        for (int h = 0; h < HD; h++)
            acc2 = fmaf(fmaxf(pi[h] + pj[h] + sb1[h], 0.0f), sw2[h], acc2);
        vbuf[p] = acc2 + bias2;
    }
    __syncthreads();

    for (int o = tid; o < nb * 100; o += 256) {
        int bb = o / 100, cell = o - bb * 100;
        int n1 = cell / 10, n2 = cell % 10;
        float val = 0.0f;
        if (n1 != n2) {
            int i = n1 < n2 ? n1 : n2;
            int j = n1 < n2 ? n2 : n1;
            val = vbuf[bb * 45 + 9 * i - (i * (i - 1)) / 2 + (j - i - 1)];
        }
        out[(cta * BPC + bb) * 100 + cell] = val;
    }
}

extern "C" void kernel_launch(void* const* d_in, const int* in_sizes, int n_in,
                              void* d_out, int out_size) {
    const float* X  = (const float*)d_in[0];
    const float* W1 = (const float*)d_in[1];
    const float* b1 = (const float*)d_in[2];
    const float* W2 = (const float*)d_in[3];
    const float* b2 = (const float*)d_in[4];
    float* out = (float*)d_out;

    cudaFuncSetAttribute(gemm_pair_kernel,
                         cudaFuncAttributeMaxDynamicSharedMemorySize, SMEM_BYTES);

    convB_kernel<<<(KD * NC + 255) / 256, 256>>>(W1);
    gemm_pair_kernel<<<NCTA, 256, SMEM_BYTES>>>(X, b1, W2, b2, out);
}